// round 16
// baseline (speedup 1.0000x reference)
#include <cuda_runtime.h>
#include <math.h>

#define PI_D 3.14159265358979323846
#define CS 65              // padded stride for smem tables / fields
#define NTHR 256

typedef unsigned long long u64;

// packed f32x2 helpers (sm_100+ PTX)
#define FMA2(acc, a, b) asm("fma.rn.f32x2 %0, %1, %2, %0;" : "+l"(acc) : "l"(a), "l"(b))
#define FMA2_3(d, a, b, c) asm("fma.rn.f32x2 %0, %1, %2, %3;" : "=l"(d) : "l"(a), "l"(b), "l"(c))
#define MUL2(d, a, b) asm("mul.rn.f32x2 %0, %1, %2;" : "=l"(d) : "l"(a), "l"(b))
#define ADD2(d, a, b) asm("add.rn.f32x2 %0, %1, %2;" : "=l"(d) : "l"(a), "l"(b))
#define PACK2(d, lo, hi) asm("mov.b64 %0, {%1, %2};" : "=l"(d) : "r"(__float_as_uint(lo)), "r"(__float_as_uint(hi)))
#define UNPACK2(lo, hi, s) do { unsigned _l, _h; \
    asm("mov.b64 {%0, %1}, %2;" : "=r"(_l), "=r"(_h) : "l"(s)); \
    lo = __uint_as_float(_l); hi = __uint_as_float(_h); } while (0)
// d = a - b  (packed), using NEG1 = (-1,-1)
#define SUB2(d, a, bb, NEG) asm("fma.rn.f32x2 %0, %1, %2, %3;" : "=l"(d) : "l"(bb), "l"(NEG), "l"(a))
// pairwise combine across lanes (2p, 2p+1)
#define SHFL_ADD2(acc) do { u64 _o = __shfl_xor_sync(0xffffffffu, acc, 1); ADD2(acc, acc, _o); } while (0)

__device__ float2 gCS[33*64];   // (cos, sin)(2*pi*k*n/65)
__device__ int    g_env_bad;    // 1 if env buffer is int32, 0 if int64

__global__ void init_tables_kernel() {
    int idx = blockIdx.x*blockDim.x + threadIdx.x;
    if (idx == 0) g_env_bad = 0;
    if (idx < 33*64) {
        int k = idx >> 6, n = idx & 63;
        double t = 2.0 * (double)(k*n) / 65.0;
        double s, c;
        sincospi(t, &s, &c);
        gCS[idx] = make_float2((float)c, (float)s);
    }
}

__global__ void detect_env_kernel(const long long* __restrict__ env) {
    int i = blockIdx.x*blockDim.x + threadIdx.x;
    if (i < 2048) {
        long long v = env[i];
        if (v < 0 || v >= 8) g_env_bad = 1;
    }
}

__global__ __launch_bounds__(NTHR, 3)
void turb_kernel(const float* __restrict__ y0, const void* __restrict__ envp,
                 const float* __restrict__ params, const float* __restrict__ domain,
                 float* __restrict__ out)
{
    extern __shared__ float smf[];
    float2* cs2  = (float2*)smf;            // [33][CS] packed (c,s): 4290 floats
    float*  xs   = smf + 4290;              // [64][CS] floats: 4160
    float*  bufA = smf + 8450;              // 4290 floats (T2 / V2)
    float*  bufB = smf + 12740;             // 4290 floats (AB scratch / u2 / psi)

    float2* T2 = (float2*)bufA;             // [64][33]
    float2* V2 = (float2*)bufA;             // [33][CS]
    float2* u2 = (float2*)bufB;             // [33][CS]
    float2* ABs = (float2*)bufB;            // [32 n][64 m] stage-1 scratch
    float*  psi = bufB;                     // [64][CS]

    const int tid = threadIdx.x;
    const int b   = blockIdx.x;

    int e;
    if (g_env_bad) e = ((const int*)envp)[b];
    else           e = (int)(((const long long*)envp)[b]);
    const float fdx  = domain[e] * (float)(PI_D / 64.0);
    const float mu   = params[2*e];
    const float fdx2 = fdx * fdx;

    // only columns 0..32 of the table are ever read
    for (int i = tid; i < 33*33; i += NTHR) {
        int k = i / 33, n = i % 33;
        cs2[k*CS + n] = gCS[(k<<6) + n];
    }
    const float* xin = y0 + (size_t)b * 4096;
    for (int i = tid; i < 4096; i += NTHR)
        xs[(i>>6)*CS + (i & 63)] = xin[i];
    __syncthreads();

    // ---------- Stage 1 prep: AB[n][m] = (x[m][n]+x[m][n2], x[m][n]-x[m][n2]) ---
    // n = 1..32, n2 = (65-n)&63 (pad wrap). Lives in bufB (dead until stage 2).
    {
        #pragma unroll
        for (int i = 0; i < 8; i++) {
            int idx = tid + i*NTHR;          // 0..2047
            int n = (idx >> 6) + 1;          // 1..32
            int m = idx & 63;
            int n2 = (65 - n) & 63;
            float x1 = xs[m*CS + n], x2 = xs[m*CS + n2];
            ABs[idx] = make_float2(x1 + x2, x1 - x2);
        }
    }
    __syncthreads();

    // ---------- Stage 1: T[m][k] = sum_{n} xpad[m][n]*(c - i s), k=0..32 --------
    // P=(sum c*A, sum s*B); T = (P.lo + x0, -P.hi).
    // Tile: thread = (mg 0..31, kg 0..7); m in {mg,mg+32}, k = kg+8*jj (k<=32).
    {
        const int mg = tid & 31;
        const int kg = tid >> 5;
        u64 P0[5], P1[5];
        #pragma unroll
        for (int j = 0; j < 5; j++) { P0[j] = 0ULL; P1[j] = 0ULL; }
        #pragma unroll 2
        for (int n = 1; n <= 32; n++) {
            u64 AB0 = *(const u64*)(ABs + (n-1)*64 + mg);
            u64 AB1 = *(const u64*)(ABs + (n-1)*64 + mg + 32);
            #pragma unroll
            for (int jj = 0; jj < 5; jj++) {
                if (jj < 4 || kg == 0) {
                    int k = kg + 8*jj;
                    u64 cs = *(const u64*)(cs2 + k*CS + n);
                    FMA2(P0[jj], AB0, cs);   // (sum c*A, sum s*B)
                    FMA2(P1[jj], AB1, cs);
                }
            }
        }
        float x00 = xs[mg*CS], x01 = xs[(mg+32)*CS];   // n=0 single: +(x0, 0)
        #pragma unroll
        for (int jj = 0; jj < 5; jj++) {
            if (jj < 4 || kg == 0) {
                int k = kg + 8*jj;
                float plo, phi; UNPACK2(plo, phi, P0[jj]);
                T2[mg*33 + k] = make_float2(plo + x00, -phi);
                UNPACK2(plo, phi, P1[jj]);
                T2[(mg+32)*33 + k] = make_float2(plo + x01, -phi);
            }
        }
    }
    __syncthreads();

    // ---------- Stage 2: wf[a][bc] = sum_{m=0..64} e^{-2pi i a m/65} Tpad[m][bc] -
    // m-fold over (m, 65-m); OUTPUT fold bc=col / 65-col shares P,Q.
    // SPLIT-K: lane pair (2p, 2p+1): half 0 sums m=1..16, half 1 m=17..32;
    // combine via shfl.xor(1)+ADD2. Epilogue: half 0 writes col, half 1 mirror.
    // Tile 3a x 3col per pair: 121 valid pairs (apg 0..10, colg 0..10).
    {
        const int half = tid & 1;
        const int pair = tid >> 1;            // 0..127
        const int colg = pair % 11;
        const int apg  = pair / 11;           // 0..11; >=11 garbage lanes
        const bool valid = (apg < 11);
        const int a0 = valid ? 3*apg : 30;
        const int c0 = 3*colg;                // colg<=10 always -> c0<=30
        u64 P[3][3], Q[3][3];
        #pragma unroll
        for (int aa = 0; aa < 3; aa++)
            #pragma unroll
            for (int cc = 0; cc < 3; cc++) { P[aa][cc] = 0ULL; Q[aa][cc] = 0ULL; }
        const int mlo = 1 + half*16;
        #pragma unroll 2
        for (int m = mlo; m < mlo + 16; m++) {
            int m2 = (65 - m) & 63;           // 64 -> 0 (pad wrap), else 65-m
            u64 CSa0 = *(const u64*)(cs2 + (a0+0)*CS + m);
            u64 CSa1 = *(const u64*)(cs2 + (a0+1)*CS + m);
            u64 CSa2 = *(const u64*)(cs2 + (a0+2)*CS + m);
            const float2* Tr1 = T2 + m*33;
            const float2* Tr2 = T2 + m2*33;
            #pragma unroll
            for (int cc = 0; cc < 3; cc++) {
                float2 t1 = Tr1[c0+cc];
                float2 t2 = Tr2[c0+cc];
                u64 Pop; PACK2(Pop, t1.x + t2.x, t1.y - t2.y);
                u64 Qop; PACK2(Qop, t1.y + t2.y, t1.x - t2.x);
                FMA2(P[0][cc], Pop, CSa0);   // (sum c*Sr, sum s*Di)
                FMA2(Q[0][cc], Qop, CSa0);   // (sum c*Si, sum s*Dr)
                FMA2(P[1][cc], Pop, CSa1);
                FMA2(Q[1][cc], Qop, CSa1);
                FMA2(P[2][cc], Pop, CSa2);
                FMA2(Q[2][cc], Qop, CSa2);
            }
        }
        #pragma unroll
        for (int aa = 0; aa < 3; aa++)
            #pragma unroll
            for (int cc = 0; cc < 3; cc++) { SHFL_ADD2(P[aa][cc]); SHFL_ADD2(Q[aa][cc]); }
        if (valid) {
            const float K2f = (float)((2.0*PI_D/65.0) * (2.0*PI_D/65.0));
            #pragma unroll
            for (int cc = 0; cc < 3; cc++) {
                int col = c0 + cc;
                float2 T0 = T2[col];            // m = 0 single term
                float col2 = (float)(col*col);
                #pragma unroll
                for (int aa = 0; aa < 3; aa++) {
                    int a = a0 + aa;
                    float plo, phi; UNPACK2(plo, phi, P[aa][cc]);
                    float qlo, qhi; UNPACK2(qlo, qhi, Q[aa][cc]);
                    float c2 = K2f * ((float)(a*a) + col2);
                    float sval = (a == 0 && col == 0) ? 0.f
                               : 1.0f / ((1e-12f + c2 / fdx2) * 4225.0f);
                    if (half == 0) {
                        float wr1 = plo + phi + T0.x;
                        float wi1 = qlo - qhi + T0.y;
                        u2[a*CS + col] = make_float2(wr1*sval, wi1*sval);
                    } else if (col > 0) {
                        float wr2 = plo - phi + T0.x;
                        float wi2 = -qlo - qhi - T0.y;
                        u2[a*CS + 65 - col] = make_float2(wr2*sval, wi2*sval);
                    }
                }
            }
        }
    }
    __syncthreads();

    // ---------- Stage 3: V[a][n] = sum_{b=0..64} u[a][b] * e^{+2πibn/65} --------
    // b-fold (b, 65-b); OUTPUT fold n / 65-n shares P,Q. SPLIT-K as stage 2.
    {
        const int half = tid & 1;
        const int pair = tid >> 1;
        const int colg = pair % 11;
        const int apg  = pair / 11;
        const bool valid = (apg < 11);
        const int a0 = valid ? 3*apg : 30;
        const int n0 = 3*colg;
        u64 P[3][3], Q[3][3];
        #pragma unroll
        for (int aa = 0; aa < 3; aa++)
            #pragma unroll
            for (int cc = 0; cc < 3; cc++) { P[aa][cc] = 0ULL; Q[aa][cc] = 0ULL; }
        const float2* ua0 = u2 + (a0+0)*CS;
        const float2* ua1 = u2 + (a0+1)*CS;
        const float2* ua2 = u2 + (a0+2)*CS;
        const int blo = 1 + half*16;
        #pragma unroll 2
        for (int bq = blo; bq < blo + 16; bq++) {
            float2 p0 = ua0[bq], q0 = ua0[65-bq];
            float2 p1 = ua1[bq], q1 = ua1[65-bq];
            float2 p2 = ua2[bq], q2 = ua2[65-bq];
            u64 A0; PACK2(A0, p0.x + q0.x, p0.y - q0.y);   // (Ar, Bi)
            u64 B0; PACK2(B0, p0.y + q0.y, p0.x - q0.x);   // (Ai, Br)
            u64 A1; PACK2(A1, p1.x + q1.x, p1.y - q1.y);
            u64 B1; PACK2(B1, p1.y + q1.y, p1.x - q1.x);
            u64 A2; PACK2(A2, p2.x + q2.x, p2.y - q2.y);
            u64 B2; PACK2(B2, p2.y + q2.y, p2.x - q2.x);
            const float2* csrow = cs2 + bq*CS + n0;
            #pragma unroll
            for (int cc = 0; cc < 3; cc++) {
                u64 cs = *(const u64*)(csrow + cc);
                FMA2(P[0][cc], A0, cs);   // (sum c*Ar, sum s*Bi)
                FMA2(Q[0][cc], B0, cs);   // (sum c*Ai, sum s*Br)
                FMA2(P[1][cc], A1, cs);
                FMA2(Q[1][cc], B1, cs);
                FMA2(P[2][cc], A2, cs);
                FMA2(Q[2][cc], B2, cs);
            }
        }
        #pragma unroll
        for (int aa = 0; aa < 3; aa++)
            #pragma unroll
            for (int cc = 0; cc < 3; cc++) { SHFL_ADD2(P[aa][cc]); SHFL_ADD2(Q[aa][cc]); }
        if (valid) {
            float2 u00 = ua0[0], u01 = ua1[0], u02 = ua2[0];   // b=0 single
            #pragma unroll
            for (int aa = 0; aa < 3; aa++) {
                int a = a0 + aa;
                float2 u0 = (aa == 0) ? u00 : ((aa == 1) ? u01 : u02);
                #pragma unroll
                for (int cc = 0; cc < 3; cc++) {
                    int n = n0 + cc;
                    float plo, phi; UNPACK2(plo, phi, P[aa][cc]);
                    float qlo, qhi; UNPACK2(qlo, qhi, Q[aa][cc]);
                    if (half == 0) {
                        V2[a*CS + n] = make_float2(plo - phi + u0.x, qlo + qhi + u0.y);
                    } else if (n >= 2) {
                        V2[a*CS + 65 - n] = make_float2(plo + phi + u0.x, qlo - qhi + u0.y);
                    }
                }
            }
        }
    }
    __syncthreads();

    // ---------- Stage 4: psi rows, m-OUTPUT fold ---------------------------------
    // psi[m][n] = Vr[0][n] + 2*(E - O), psi[65-m][n] = Vr[0][n] + 2*(E + O)
    // with P=(E,O)=(sum c*Vr, sum s*Vi) over a=1..32.
    // Tile 3mcol x 4n: mcg = tid&15 (<11), ngq = tid>>4 (0..15).
    {
        const int mcg = tid & 15;
        const int ngq = tid >> 4;    // 0..15
        if (mcg < 11) {
            const int m0 = 3*mcg;
            u64 P[3][4];
            #pragma unroll
            for (int mm = 0; mm < 3; mm++)
                #pragma unroll
                for (int jj = 0; jj < 4; jj++) P[mm][jj] = 0ULL;
            #pragma unroll 2
            for (int a = 1; a < 33; a++) {
                u64 C0 = *(const u64*)(cs2 + a*CS + m0 + 0);
                u64 C1 = *(const u64*)(cs2 + a*CS + m0 + 1);
                u64 C2 = *(const u64*)(cs2 + a*CS + m0 + 2);
                const float2* Vrow = V2 + a*CS + ngq*4;
                #pragma unroll
                for (int jj = 0; jj < 4; jj++) {
                    u64 V = *(const u64*)(Vrow + jj);
                    FMA2(P[0][jj], C0, V);       // (c*Vr, s*Vi)
                    FMA2(P[1][jj], C1, V);
                    FMA2(P[2][jj], C2, V);
                }
            }
            #pragma unroll
            for (int jj = 0; jj < 4; jj++) {
                int n = ngq*4 + jj;
                float v0r = V2[n].x;
                #pragma unroll
                for (int mm = 0; mm < 3; mm++) {
                    int mcol = m0 + mm;
                    float plo, phi; UNPACK2(plo, phi, P[mm][jj]);
                    psi[mcol*CS + n] = v0r + 2.0f*(plo - phi);
                    if (mcol >= 2)
                        psi[(65 - mcol)*CS + n] = v0r + 2.0f*(plo + phi);
                }
            }
        }
    }
    __syncthreads();

    // ---------- Stencil: Arakawa Jacobian + laplacian, packed column pairs ------
    // Thread handles outputs (i, j) and (i, j+1), j even. All math in f32x2.
    {
        float* o = out + (size_t)b * 4096;
        const float inv12 = 1.0f / (12.0f * fdx2);   // (1/(4 fdx2)) / 3
        const float mf    = mu / fdx2;
        u64 NEG1;  PACK2(NEG1,  -1.0f, -1.0f);
        u64 NFOUR; PACK2(NFOUR, -4.0f, -4.0f);
        u64 NINV12; PACK2(NINV12, -inv12, -inv12);
        u64 MF2;   PACK2(MF2, mf, mf);
        #pragma unroll 2
        for (int t = 0; t < 8; t++) {
            int pidx = tid + t*NTHR;          // 0..2047
            int i = pidx >> 5;                // row 0..63
            int j = (pidx & 31) << 1;         // even col 0..62
            int ip = (i+1) & 63, im = (i-1) & 63;
            int jm = (j-1) & 63, jp2 = (j+2) & 63;   // j+1 <= 63 always
            const float* Pi = psi + i*CS;  const float* Pp = psi + ip*CS;  const float* Pm = psi + im*CS;
            const float* Xi = xs  + i*CS;  const float* Xp = xs  + ip*CS;  const float* Xm = xs  + im*CS;
            float pi_m = Pi[jm], pi_0 = Pi[j], pi_1 = Pi[j+1], pi_2 = Pi[jp2];
            float pp_m = Pp[jm], pp_0 = Pp[j], pp_1 = Pp[j+1], pp_2 = Pp[jp2];
            float pm_m = Pm[jm], pm_0 = Pm[j], pm_1 = Pm[j+1], pm_2 = Pm[jp2];
            float xi_m = Xi[jm], xi_0 = Xi[j], xi_1 = Xi[j+1], xi_2 = Xi[jp2];
            float xp_m = Xp[jm], xp_0 = Xp[j], xp_1 = Xp[j+1], xp_2 = Xp[jp2];
            float xm_m = Xm[jm], xm_0 = Xm[j], xm_1 = Xm[j+1], xm_2 = Xm[jp2];
            u64 Pipj;  PACK2(Pipj,  pp_0, pp_1);
            u64 Pimj;  PACK2(Pimj,  pm_0, pm_1);
            u64 Pijp;  PACK2(Pijp,  pi_1, pi_2);
            u64 Pijm;  PACK2(Pijm,  pi_m, pi_0);
            u64 Pipjp; PACK2(Pipjp, pp_1, pp_2);
            u64 Pipjm; PACK2(Pipjm, pp_m, pp_0);
            u64 Pimjp; PACK2(Pimjp, pm_1, pm_2);
            u64 Pimjm; PACK2(Pimjm, pm_m, pm_0);
            u64 Xc2;   PACK2(Xc2,   xi_0, xi_1);
            u64 Xipj;  PACK2(Xipj,  xp_0, xp_1);
            u64 Ximj;  PACK2(Ximj,  xm_0, xm_1);
            u64 Xijp;  PACK2(Xijp,  xi_1, xi_2);
            u64 Xijm;  PACK2(Xijm,  xi_m, xi_0);
            u64 Xipjp; PACK2(Xipjp, xp_1, xp_2);
            u64 Xipjm; PACK2(Xipjm, xp_m, xp_0);
            u64 Ximjp; PACK2(Ximjp, xm_1, xm_2);
            u64 Ximjm; PACK2(Ximjm, xm_m, xm_0);
            // J1
            u64 dPj; SUB2(dPj, Pipj, Pimj, NEG1);
            u64 dXj; SUB2(dXj, Xijp, Xijm, NEG1);
            u64 dPi; SUB2(dPi, Pijp, Pijm, NEG1);
            u64 dXi; SUB2(dXi, Xipj, Ximj, NEG1);
            u64 acc; MUL2(acc, dPj, dXj);
            u64 tm;  MUL2(tm, dPi, dXi);
            SUB2(acc, acc, tm, NEG1);
            // J2
            u64 d1; SUB2(d1, Pipjp, Pimjp, NEG1);
            u64 d2; SUB2(d2, Pipjm, Pimjm, NEG1);
            u64 d3; SUB2(d3, Pipjp, Pipjm, NEG1);
            u64 d4; SUB2(d4, Pimjp, Pimjm, NEG1);
            FMA2_3(acc, Xijp, d1, acc);
            MUL2(tm, Xijm, d2); SUB2(acc, acc, tm, NEG1);
            MUL2(tm, Xipj, d3); SUB2(acc, acc, tm, NEG1);
            FMA2_3(acc, Ximj, d4, acc);
            // J3
            u64 e1; SUB2(e1, Pipj, Pijp, NEG1);
            u64 e2; SUB2(e2, Pijm, Pimj, NEG1);
            u64 e3; SUB2(e3, Pipj, Pijm, NEG1);
            u64 e4; SUB2(e4, Pijp, Pimj, NEG1);
            FMA2_3(acc, Xipjp, e1, acc);
            MUL2(tm, Ximjm, e2); SUB2(acc, acc, tm, NEG1);
            MUL2(tm, Xipjm, e3); SUB2(acc, acc, tm, NEG1);
            FMA2_3(acc, Ximjp, e4, acc);
            // laplacian = Ximj + Xijm - 4*Xc + Xijp + Xipjm + Xipj
            u64 lap; ADD2(lap, Ximj, Xijm);
            ADD2(lap, lap, Xijp);
            ADD2(lap, lap, Xipjm);
            ADD2(lap, lap, Xipj);
            FMA2_3(lap, Xc2, NFOUR, lap);
            // out = -(J1+J2+J3)*inv12 + mf*lap
            u64 res; MUL2(res, lap, MF2);
            FMA2_3(res, acc, NINV12, res);
            float rlo, rhi; UNPACK2(rlo, rhi, res);
            *(float2*)(o + i*64 + j) = make_float2(rlo, rhi);
        }
    }
}

extern "C" void kernel_launch(void* const* d_in, const int* in_sizes, int n_in,
                              void* d_out, int out_size) {
    // inputs (metadata order): t, y0, env, codes, params, domain
    const float* y0     = (const float*)d_in[1];
    const void*  envp   = d_in[2];
    const float* params = (const float*)d_in[4];
    const float* domain = (const float*)d_in[5];
    float* out = (float*)d_out;

    const int smemBytes = 17030 * (int)sizeof(float); // 68120 B
    cudaFuncSetAttribute(turb_kernel, cudaFuncAttributeMaxDynamicSharedMemorySize, smemBytes);

    init_tables_kernel<<<9, 256>>>();
    detect_env_kernel<<<8, 256>>>((const long long*)envp);
    turb_kernel<<<4096, NTHR, smemBytes>>>(y0, envp, params, domain, out);
}